// round 13
// baseline (speedup 1.0000x reference)
#include <cuda_runtime.h>
#include <cuda_fp16.h>
#include <math.h>
#include <cstdint>

#define B_    2
#define C_    64
#define T_    3000
#define F_    65
#define H_    4
#define D_    4
#define E_    16
#define DF    260
#define KQK   288      // QK K-dim padded (mult of 32)
#define EF    1040
#define NPV   1152     // V storage row width (pad cols zero)
#define KPV   3008     // PV K-dim padded (mult of 64); also P row width
#define TMPAD 3072     // M padded (mult of 128)
#define TNP   3072     // QK N tile range
#define PTS   195000   // T_*F_ points per batch
#define BH    8
#define EPS   1e-5f

// ---------------- scratch (zero-initialized .bss; pads rely on that + writes)
__device__ __align__(128) __half g_Qh [(size_t)BH * TMPAD * KQK];
__device__ __align__(128) __half g_Kh [(size_t)BH * TMPAD * KQK];
__device__ __align__(128) __half g_P  [(size_t)BH * TMPAD * KPV];  // exp(S), unnormalized
__device__ __align__(128) __half g_Vn [(size_t)BH * KPV * NPV];    // V (fp16)
__device__ __align__(128) __half g_Ohn[(size_t)BH * T_ * EF];      // normalized O, fp16
__device__ __align__(128) float  g_rsum[(size_t)BH * TMPAD];       // softmax row sums

// ---------------- helpers ----------------------------------------------------
__device__ __forceinline__ uint32_t smem_u32(const void* p) {
    uint32_t a;
    asm("{ .reg .u64 t; cvta.to.shared.u64 t, %1; cvt.u32.u64 %0, t; }" : "=r"(a) : "l"(p));
    return a;
}
__device__ __forceinline__ void cpa16(uint32_t s, const void* g) {
    asm volatile("cp.async.cg.shared.global [%0], [%1], 16;" :: "r"(s), "l"(g));
}
__device__ __forceinline__ void ldm4(uint32_t* r, uint32_t a) {
    asm volatile("ldmatrix.sync.aligned.m8n8.x4.shared.b16 {%0,%1,%2,%3}, [%4];"
                 : "=r"(r[0]), "=r"(r[1]), "=r"(r[2]), "=r"(r[3]) : "r"(a));
}
__device__ __forceinline__ void ldm4t(uint32_t* r, uint32_t a) {
    asm volatile("ldmatrix.sync.aligned.m8n8.x4.trans.shared.b16 {%0,%1,%2,%3}, [%4];"
                 : "=r"(r[0]), "=r"(r[1]), "=r"(r[2]), "=r"(r[3]) : "r"(a));
}
__device__ __forceinline__ void mma16816(float* c, const uint32_t* a, const uint32_t* b) {
    asm volatile("mma.sync.aligned.m16n8k16.row.col.f32.f16.f16.f32 "
                 "{%0,%1,%2,%3}, {%4,%5,%6,%7}, {%8,%9}, {%0,%1,%2,%3};"
                 : "+f"(c[0]), "+f"(c[1]), "+f"(c[2]), "+f"(c[3])
                 : "r"(a[0]), "r"(a[1]), "r"(a[2]), "r"(a[3]), "r"(b[0]), "r"(b[1]));
}

// ---- packed f32x2 helpers (FFMA2: rt 1/SMSP vs 2 for 3-reg FFMA) ----
__device__ __forceinline__ unsigned long long pk2(float lo, float hi) {
    unsigned long long r;
    asm("mov.b64 %0, {%1,%2};" : "=l"(r) : "f"(lo), "f"(hi));
    return r;
}
// dot64 against smem weight row using packed f32x2 FMAs (exact fp32 semantics).
__device__ __forceinline__ float dot64p(const float* wrow, const unsigned long long* v2) {
    const unsigned long long* w2 = reinterpret_cast<const unsigned long long*>(wrow);
    unsigned long long a01 = 0ull, a23 = 0ull;   // (0.f,0.f) bit pattern
#pragma unroll
    for (int i = 0; i < 16; i++) {
        asm("fma.rn.f32x2 %0, %1, %2, %0;" : "+l"(a01) : "l"(w2[2 * i]),     "l"(v2[2 * i]));
        asm("fma.rn.f32x2 %0, %1, %2, %0;" : "+l"(a23) : "l"(w2[2 * i + 1]), "l"(v2[2 * i + 1]));
    }
    float l0, h0, l1, h1;
    asm("mov.b64 {%0,%1}, %2;" : "=f"(l0), "=f"(h0) : "l"(a01));
    asm("mov.b64 {%0,%1}, %2;" : "=f"(l1), "=f"(h1) : "l"(a23));
    return (l0 + h0) + (l1 + h1);
}

// ============================================================================
// Kernel 1a: Q/K 1x1-conv + PReLU + channel-LN -> fp16. Also zeroes g_rsum.
// ============================================================================
__global__ void k_projqk(const float* __restrict__ x,
                       const float* __restrict__ Wq, const float* __restrict__ bq,
                       const float* __restrict__ aq, const float* __restrict__ gq,
                       const float* __restrict__ betaq,
                       const float* __restrict__ Wk, const float* __restrict__ bk,
                       const float* __restrict__ ak, const float* __restrict__ gk,
                       const float* __restrict__ betak) {
    __shared__ float sWq[H_ * D_ * C_];
    __shared__ float sWk[H_ * D_ * C_];
    int tid = threadIdx.x;
    for (int i = tid; i < H_ * D_ * C_; i += blockDim.x) { sWq[i] = Wq[i]; sWk[i] = Wk[i]; }
    __syncthreads();

    int p = blockIdx.x * blockDim.x + tid;
    if (p < BH * TMPAD) g_rsum[p] = 0.f;
    const int P = B_ * T_ * F_;
    if (p >= P) return;
    int b = p / (T_ * F_);
    int r = p % (T_ * F_);
    int t = r / F_;
    int f = r % F_;

    unsigned long long xv2[C_ / 2];
#pragma unroll
    for (int c = 0; c < C_; c += 2) {
        float v0 = x[((size_t)(b * C_ + c) * T_ + t) * F_ + f];
        float v1 = x[((size_t)(b * C_ + c + 1) * T_ + t) * F_ + f];
        xv2[c >> 1] = pk2(v0, v1);
    }

    const __half hz = __float2half(0.0f);
    for (int h = 0; h < H_; h++) {
        int bh = b * H_ + h;
        {
            float q[D_];
            float ah = aq[h];
#pragma unroll
            for (int d = 0; d < D_; d++) {
                float acc = bq[h * D_ + d] + dot64p(&sWq[(h * D_ + d) * C_], xv2);
                q[d] = acc >= 0.f ? acc : ah * acc;
            }
            float mu = 0.f, s2 = 0.f;
#pragma unroll
            for (int d = 0; d < D_; d++) { mu += q[d]; s2 += q[d] * q[d]; }
            mu *= (1.f / D_);
            s2 = s2 * (1.f / D_) - mu * mu;
            float inv = rsqrtf(s2 + EPS);
            size_t base = ((size_t)bh * TMPAD + t) * KQK;
#pragma unroll
            for (int d = 0; d < D_; d++)
                g_Qh[base + d * F_ + f] =
                    __float2half((q[d] - mu) * inv * gq[h * D_ + d] + betaq[h * D_ + d]);
            if (f < KQK - DF) g_Qh[base + DF + f] = hz;
        }
        {
            float q[D_];
            float ah = ak[h];
#pragma unroll
            for (int d = 0; d < D_; d++) {
                float acc = bk[h * D_ + d] + dot64p(&sWk[(h * D_ + d) * C_], xv2);
                q[d] = acc >= 0.f ? acc : ah * acc;
            }
            float mu = 0.f, s2 = 0.f;
#pragma unroll
            for (int d = 0; d < D_; d++) { mu += q[d]; s2 += q[d] * q[d]; }
            mu *= (1.f / D_);
            s2 = s2 * (1.f / D_) - mu * mu;
            float inv = rsqrtf(s2 + EPS);
            size_t base = ((size_t)bh * TMPAD + t) * KQK;
#pragma unroll
            for (int d = 0; d < D_; d++)
                g_Kh[base + d * F_ + f] =
                    __float2half((q[d] - mu) * inv * gk[h * D_ + d] + betak[h * D_ + d]);
            if (f < KQK - DF) g_Kh[base + DF + f] = hz;
        }
    }
}

// ============================================================================
// Kernel 1b: V 1x1-conv + PReLU + channel-LN -> fp16 (overlaps with k_qk).
// ============================================================================
__global__ void k_projv(const float* __restrict__ x,
                       const float* __restrict__ Wv, const float* __restrict__ bv,
                       const float* __restrict__ av, const float* __restrict__ gv,
                       const float* __restrict__ betav) {
    __shared__ float sWv[H_ * E_ * C_];
    int tid = threadIdx.x;
    for (int i = tid; i < H_ * E_ * C_; i += blockDim.x) sWv[i] = Wv[i];
    __syncthreads();

    int p = blockIdx.x * blockDim.x + tid;
    const int P = B_ * T_ * F_;
    if (p >= P) return;
    int b = p / (T_ * F_);
    int r = p % (T_ * F_);
    int t = r / F_;
    int f = r % F_;

    unsigned long long xv2[C_ / 2];
#pragma unroll
    for (int c = 0; c < C_; c += 2) {
        float v0 = x[((size_t)(b * C_ + c) * T_ + t) * F_ + f];
        float v1 = x[((size_t)(b * C_ + c + 1) * T_ + t) * F_ + f];
        xv2[c >> 1] = pk2(v0, v1);
    }

    for (int h = 0; h < H_; h++) {
        int bh = b * H_ + h;
        float v[E_];
        float ah = av[h];
#pragma unroll
        for (int e = 0; e < E_; e++) {
            float acc = bv[h * E_ + e] + dot64p(&sWv[(h * E_ + e) * C_], xv2);
            v[e] = acc >= 0.f ? acc : ah * acc;
        }
        float mu = 0.f, s2 = 0.f;
#pragma unroll
        for (int e = 0; e < E_; e++) { mu += v[e]; s2 += v[e] * v[e]; }
        mu *= (1.f / E_);
        s2 = s2 * (1.f / E_) - mu * mu;
        float inv = rsqrtf(s2 + EPS);
        size_t base = ((size_t)bh * KPV + t) * NPV;
#pragma unroll
        for (int e = 0; e < E_; e++)
            g_Vn[base + e * F_ + f] =
                __float2half((v[e] - mu) * inv * gv[h * E_ + e] + betav[h * E_ + e]);
    }
}

// ============================================================================
// Kernel 2a: QK GEMM. CTA 128x128, 4 warps (2m x 2n), warp tile 64x64,
// BK=32, 4-stage. P = fp16(exp(scale*acc)) + rsum atomics. (unchanged R11)
// ============================================================================
#define QK_ASTG 10240
#define QK_BROW 80
#define QK_STG  (QK_ASTG + 128 * QK_BROW)   // 20480
#define QK_NSTAGE 4

__global__ void __launch_bounds__(128, 2) k_qk(float scale) {
    extern __shared__ __align__(128) char smem[];
    const int tid = threadIdx.x;
    const int wid = tid >> 5, lane = tid & 31;
    const int wm = wid & 1, wn = wid >> 1;     // 2m x 2n
    const int bh = blockIdx.z, m0 = blockIdx.y * 128, n0 = blockIdx.x * 128;

    const __half* Ag = g_Qh + (size_t)bh * TMPAD * KQK;
    const __half* Bg = g_Kh + (size_t)bh * TMPAD * KQK;
    const int chunks = KQK / 32;   // 9

    const uint32_t sbase = smem_u32(smem);

    float acc[4][8][4];
#pragma unroll
    for (int i = 0; i < 4; i++)
#pragma unroll
        for (int j = 0; j < 8; j++)
#pragma unroll
            for (int q = 0; q < 4; q++) acc[i][j][q] = 0.f;

    auto load_stage = [&](int st, int c) {
        uint32_t sa = sbase + st * QK_STG;
        uint32_t sb = sa + QK_ASTG;
        int k0 = c * 32;
#pragma unroll
        for (int j = 0; j < 4; j++) {
            int idx = tid + j * 128;
            int row = idx >> 2, g = idx & 3;
            cpa16(sa + row * 80 + g * 16, Ag + (size_t)(m0 + row) * KQK + k0 + g * 8);
            cpa16(sb + row * 80 + g * 16, Bg + (size_t)(n0 + row) * KQK + k0 + g * 8);
        }
    };

    auto compute_stage = [&](int st) {
        uint32_t sa = sbase + st * QK_STG;
        uint32_t sb = sa + QK_ASTG;
#pragma unroll
        for (int kk = 0; kk < 32; kk += 16) {
            uint32_t a[4][4];
#pragma unroll
            for (int mt = 0; mt < 4; mt++) {
                int row = wm * 64 + mt * 16 + (lane & 15);
                ldm4(a[mt], sa + row * 80 + (kk + ((lane >> 4) << 3)) * 2);
            }
            uint32_t bfr[4][4];
#pragma unroll
            for (int bt = 0; bt < 4; bt++) {
                int row = wn * 64 + bt * 16 + ((lane >> 4) << 3) + (lane & 7);
                ldm4(bfr[bt], sb + row * 80 + (kk + ((lane >> 3) & 1) * 8) * 2);
            }
#pragma unroll
            for (int mt = 0; mt < 4; mt++)
#pragma unroll
                for (int nt = 0; nt < 8; nt++)
                    mma16816(acc[mt][nt], a[mt], &bfr[nt >> 1][(nt & 1) * 2]);
        }
    };

    load_stage(0, 0);
    asm volatile("cp.async.commit_group;" ::: "memory");
    load_stage(1, 1);
    asm volatile("cp.async.commit_group;" ::: "memory");
    load_stage(2, 2);
    asm volatile("cp.async.commit_group;" ::: "memory");

    int st = 0;
    for (int c = 0; c < chunks; c++) {
        if (c >= chunks - 1)      asm volatile("cp.async.wait_group 0;" ::: "memory");
        else if (c == chunks - 2) asm volatile("cp.async.wait_group 1;" ::: "memory");
        else                      asm volatile("cp.async.wait_group 2;" ::: "memory");
        __syncthreads();
        if (c + 3 < chunks) {
            int st2 = st + 3; if (st2 >= QK_NSTAGE) st2 -= QK_NSTAGE;
            load_stage(st2, c + 3);
            asm volatile("cp.async.commit_group;" ::: "memory");
        } else {
            asm volatile("cp.async.commit_group;" ::: "memory");
        }
        compute_stage(st);
        if (++st == QK_NSTAGE) st = 0;
    }

    // epilogue: exp, store P, rsum atomics
#pragma unroll
    for (int mt = 0; mt < 4; mt++) {
        int r0 = m0 + wm * 64 + mt * 16 + (lane >> 2);
        float rs0 = 0.f, rs1 = 0.f;
#pragma unroll
        for (int nt = 0; nt < 8; nt++) {
            int cc = n0 + wn * 64 + nt * 8 + (lane & 3) * 2;
            float* a4 = acc[mt][nt];
            float e0 = (cc     < T_) ? __expf(a4[0] * scale) : 0.f;
            float e1 = (cc + 1 < T_) ? __expf(a4[1] * scale) : 0.f;
            float e2 = (cc     < T_) ? __expf(a4[2] * scale) : 0.f;
            float e3 = (cc + 1 < T_) ? __expf(a4[3] * scale) : 0.f;
            rs0 += e0 + e1;
            rs1 += e2 + e3;
            if (cc < KPV) {
                __half2 h0, h1;
                h0.x = __float2half(e0); h0.y = __float2half(e1);
                h1.x = __float2half(e2); h1.y = __float2half(e3);
                *reinterpret_cast<__half2*>(&g_P[((size_t)bh * TMPAD + r0) * KPV + cc]) = h0;
                *reinterpret_cast<__half2*>(&g_P[((size_t)bh * TMPAD + r0 + 8) * KPV + cc]) = h1;
            }
        }
        rs0 += __shfl_xor_sync(~0u, rs0, 1); rs0 += __shfl_xor_sync(~0u, rs0, 2);
        rs1 += __shfl_xor_sync(~0u, rs1, 1); rs1 += __shfl_xor_sync(~0u, rs1, 2);
        if ((lane & 3) == 0) {
            atomicAdd(&g_rsum[bh * TMPAD + r0], rs0);
            atomicAdd(&g_rsum[bh * TMPAD + r0 + 8], rs1);
        }
    }
}

// ============================================================================
// Kernel 2b: PV GEMM. CTA 128x96, 4 warps (2m x 2n), warp tile 64x48,
// BK=64, 3-stage. (R11 config: launch_bounds(128,2), regs free.)
// ============================================================================
#define PV_AROW 144
#define PV_ASTG (128 * PV_AROW)      // 18432
#define PV_BROW 208
#define PV_BSTG (64 * PV_BROW)       // 13312
#define PV_STG  (PV_ASTG + PV_BSTG)  // 31744
#define PV_NSTAGE 3

__global__ void __launch_bounds__(128, 2) k_pv() {
    extern __shared__ __align__(128) char smem[];
    const int tid = threadIdx.x;
    const int wid = tid >> 5, lane = tid & 31;
    const int wm = wid & 1, wn = wid >> 1;     // 2m x 2n
    const int bh = blockIdx.z, m0 = blockIdx.y * 128, n0 = blockIdx.x * 96;

    const __half* Ag = g_P + (size_t)bh * TMPAD * KPV;
    const __half* Bg = g_Vn + (size_t)bh * KPV * NPV;
    const int chunks = KPV / 64;    // 47

    const uint32_t sbase = smem_u32(smem);

    float acc[4][6][4];
#pragma unroll
    for (int i = 0; i < 4; i++)
#pragma unroll
        for (int j = 0; j < 6; j++)
#pragma unroll
            for (int q = 0; q < 4; q++) acc[i][j][q] = 0.f;

    auto load_stage = [&](int st, int c) {
        uint32_t sa = sbase + st * PV_STG;
        uint32_t sb = sa + PV_ASTG;
        int k0 = c * 64;
#pragma unroll
        for (int j = 0; j < 8; j++) {
            int idx = tid + j * 128;
            int row = idx >> 3, g = idx & 7;
            cpa16(sa + row * PV_AROW + g * 16, Ag + (size_t)(m0 + row) * KPV + k0 + g * 8);
        }
#pragma unroll
        for (int j = 0; j < 7; j++) {
            int idx = tid + j * 128;
            if (idx < 64 * 13) {
                int row = idx / 13, g = idx % 13;
                cpa16(sb + row * PV_BROW + g * 16, Bg + (size_t)(k0 + row) * NPV + n0 + g * 8);
            }
        }
    };

    auto compute_stage = [&](int st) {
        uint32_t sa = sbase + st * PV_STG;
        uint32_t sb = sa + PV_ASTG;
#pragma unroll
        for (int kk = 0; kk < 64; kk += 16) {
            uint32_t a[4][4];
#pragma unroll
            for (int mt = 0; mt < 4; mt++) {
                int row = wm * 64 + mt * 16 + (lane & 15);
                ldm4(a[mt], sa + row * PV_AROW + (kk + ((lane >> 4) << 3)) * 2);
            }
            uint32_t bfr[3][4];
#pragma unroll
            for (int bt = 0; bt < 3; bt++) {
                int krow = kk + (lane & 15);
                int ncol = wn * 48 + bt * 16 + ((lane >> 4) << 3);
                ldm4t(bfr[bt], sb + krow * PV_BROW + ncol * 2);
            }
#pragma unroll
            for (int mt = 0; mt < 4; mt++)
#pragma unroll
                for (int nt = 0; nt < 6; nt++)
                    mma16816(acc[mt][nt], a[mt], &bfr[nt >> 1][(nt & 1) * 2]);
        }
    };

    load_stage(0, 0);
    asm volatile("cp.async.commit_group;" ::: "memory");
    load_stage(1, 1);
    asm volatile("cp.async.commit_group;" ::: "memory");

    int st = 0;
    for (int c = 0; c < chunks; c++) {
        if (c == chunks - 1) asm volatile("cp.async.wait_group 0;" ::: "memory");
        else                 asm volatile("cp.async.wait_group 1;" ::: "memory");
        __syncthreads();
        if (c + 2 < chunks) {
            int st2 = st + 2; if (st2 >= PV_NSTAGE) st2 -= PV_NSTAGE;
            load_stage(st2, c + 2);
            asm volatile("cp.async.commit_group;" ::: "memory");
        } else {
            asm volatile("cp.async.commit_group;" ::: "memory");
        }
        compute_stage(st);
        if (++st == PV_NSTAGE) st = 0;
    }

    // epilogue: normalize by row sums, write fp16
#pragma unroll
    for (int mt = 0; mt < 4; mt++) {
        int r0 = m0 + wm * 64 + mt * 16 + (lane >> 2);
        float ri0 = 1.0f / g_rsum[bh * TMPAD + r0];
        float ri1 = 1.0f / g_rsum[bh * TMPAD + r0 + 8];
#pragma unroll
        for (int nt = 0; nt < 6; nt++) {
            int cc = n0 + wn * 48 + nt * 8 + (lane & 3) * 2;
            float* a4 = acc[mt][nt];
            if (cc < EF) {
                if (r0 < T_) {
                    __half2 h;
                    h.x = __float2half(a4[0] * ri0);
                    h.y = __float2half(a4[1] * ri0);
                    *reinterpret_cast<__half2*>(&g_Ohn[((size_t)bh * T_ + r0) * EF + cc]) = h;
                }
                if (r0 + 8 < T_) {
                    __half2 h;
                    h.x = __float2half(a4[2] * ri1);
                    h.y = __float2half(a4[3] * ri1);
                    *reinterpret_cast<__half2*>(&g_Ohn[((size_t)bh * T_ + r0 + 8) * EF + cc]) = h;
                }
            }
        }
    }
}

// ============================================================================
// Kernel 3: tensorized final conv: out = LN(PReLU(Wp @ Ohn + bp)) + x.
// ============================================================================
#define RSX 136
#define RSW 72
__global__ void __launch_bounds__(256) k_final(const float* __restrict__ x,
                        const float* __restrict__ Wp, const float* __restrict__ bp,
                        const float* __restrict__ ap, const float* __restrict__ gp,
                        const float* __restrict__ betap,
                        float* __restrict__ out) {
    __shared__ __align__(128) __half sX[64 * RSX];
    __shared__ __align__(128) __half sW[64 * RSW];
    __shared__ float sRed[2][4][128];

    const int tid = threadIdx.x;
    const int wid = tid >> 5, lane = tid & 31;
    const int wm = wid & 3, wn = wid >> 2;
    const int b = blockIdx.y, n0 = blockIdx.x * 128;

    for (int i = tid; i < C_ * C_; i += 256)
        sW[(i >> 6) * RSW + (i & 63)] = __float2half(Wp[i]);
    for (int i = tid; i < C_ * 128; i += 256) {
        int c = i >> 7, n = i & 127;
        int pp = n0 + n;
        __half v = __float2half(0.f);
        if (pp < PTS) {
            int t = pp / F_, f = pp - t * F_;
            v = g_Ohn[((size_t)(b * H_ + (c >> 4)) * T_ + t) * EF + (c & 15) * F_ + f];
        }
        sX[c * RSX + n] = v;
    }
    __syncthreads();

    const uint32_t uW = smem_u32(sW), uX = smem_u32(sX);

    uint32_t aAll[4][4];
#pragma unroll
    for (int kk = 0; kk < 4; kk++)
        ldm4(aAll[kk], uW + (wm * 16 + (lane & 15)) * (RSW * 2)
                          + (kk * 16 + ((lane >> 4) << 3)) * 2);

    float acc[8][4];
#pragma unroll
    for (int j = 0; j < 8; j++)
#pragma unroll
        for (int q = 0; q < 4; q++) acc[j][q] = 0.f;

#pragma unroll
    for (int kk = 0; kk < 4; kk++) {
        uint32_t bfr[4][4];
#pragma unroll
        for (int bt = 0; bt < 4; bt++)
            ldm4t(bfr[bt], uX + (kk * 16 + (lane & 15)) * (RSX * 2)
                              + (wn * 64 + bt * 16 + ((lane >> 4) << 3)) * 2);
#pragma unroll
        for (int nt = 0; nt < 8; nt++)
            mma16816(acc[nt], aAll[kk], &bfr[nt >> 1][(nt & 1) * 2]);
    }

    const int o = wm * 16 + (lane >> 2);
    const float b0 = bp[o], b1 = bp[o + 8];
    const float a = ap[0];
#pragma unroll
    for (int nt = 0; nt < 8; nt++) {
        float* a4 = acc[nt];
        float y0 = a4[0] + b0; y0 = y0 >= 0.f ? y0 : a * y0;
        float y1 = a4[1] + b0; y1 = y1 >= 0.f ? y1 : a * y1;
        float y2 = a4[2] + b1; y2 = y2 >= 0.f ? y2 : a * y2;
        float y3 = a4[3] + b1; y3 = y3 >= 0.f ? y3 : a * y3;
        a4[0] = y0; a4[1] = y1; a4[2] = y2; a4[3] = y3;
        float s0 = y0 + y2, s1 = y1 + y3;
        float q0 = y0 * y0 + y2 * y2, q1 = y1 * y1 + y3 * y3;
#pragma unroll
        for (int m = 4; m <= 16; m <<= 1) {
            s0 += __shfl_xor_sync(~0u, s0, m);
            s1 += __shfl_xor_sync(~0u, s1, m);
            q0 += __shfl_xor_sync(~0u, q0, m);
            q1 += __shfl_xor_sync(~0u, q1, m);
        }
        if ((lane >> 2) == 0) {
            int cl = wn * 64 + nt * 8 + (lane & 3) * 2;
            sRed[0][wm][cl] = s0; sRed[0][wm][cl + 1] = s1;
            sRed[1][wm][cl] = q0; sRed[1][wm][cl + 1] = q1;
        }
    }
    __syncthreads();

    const float g0 = gp[o], g1 = gp[o + 8];
    const float be0 = betap[o], be1 = betap[o + 8];
#pragma unroll
    for (int nt = 0; nt < 8; nt++) {
        int cl = wn * 64 + nt * 8 + (lane & 3) * 2;
        int pp = n0 + cl;
        if (pp >= PTS) continue;
        float mu0 = 0.f, mu1 = 0.f, sq0 = 0.f, sq1 = 0.f;
#pragma unroll
        for (int w = 0; w < 4; w++) {
            mu0 += sRed[0][w][cl];     mu1 += sRed[0][w][cl + 1];
            sq0 += sRed[1][w][cl];     sq1 += sRed[1][w][cl + 1];
        }
        mu0 *= (1.f / C_); mu1 *= (1.f / C_);
        float v0 = sq0 * (1.f / C_) - mu0 * mu0;
        float v1 = sq1 * (1.f / C_) - mu1 * mu1;
        float i0 = rsqrtf(v0 + EPS), i1 = rsqrtf(v1 + EPS);
        float* a4 = acc[nt];
        size_t idx0 = ((size_t)(b * C_ + o)) * PTS + pp;
        size_t idx1 = ((size_t)(b * C_ + o + 8)) * PTS + pp;
        float2 xr0 = *reinterpret_cast<const float2*>(&x[idx0]);
        float2 xr1 = *reinterpret_cast<const float2*>(&x[idx1]);
        float2 o0, o1;
        o0.x = (a4[0] - mu0) * i0 * g0 + be0 + xr0.x;
        o0.y = (a4[1] - mu1) * i1 * g0 + be0 + xr0.y;
        o1.x = (a4[2] - mu0) * i0 * g1 + be1 + xr1.x;
        o1.y = (a4[3] - mu1) * i1 * g1 + be1 + xr1.y;
        *reinterpret_cast<float2*>(&out[idx0]) = o0;
        *reinterpret_cast<float2*>(&out[idx1]) = o1;
    }
}

// ============================================================================
extern "C" void kernel_launch(void* const* d_in, const int* in_sizes, int n_in,
                              void* d_out, int out_size) {
    const float* x     = (const float*)d_in[0];
    const float* Wq    = (const float*)d_in[1];
    const float* bq    = (const float*)d_in[2];
    const float* aq    = (const float*)d_in[3];
    const float* gq    = (const float*)d_in[4];
    const float* betaq = (const float*)d_in[5];
    const float* Wk    = (const float*)d_in[6];
    const float* bk    = (const float*)d_in[7];
    const float* ak    = (const float*)d_in[8];
    const float* gk    = (const float*)d_in[9];
    const float* betak = (const float*)d_in[10];
    const float* Wv    = (const float*)d_in[11];
    const float* bv    = (const float*)d_in[12];
    const float* av    = (const float*)d_in[13];
    const float* gv    = (const float*)d_in[14];
    const float* betav = (const float*)d_in[15];
    const float* Wp    = (const float*)d_in[16];
    const float* bp    = (const float*)d_in[17];
    const float* ap    = (const float*)d_in[18];
    const float* gp    = (const float*)d_in[19];
    const float* betap = (const float*)d_in[20];
    float* out = (float*)d_out;

    static cudaStream_t s2 = nullptr;
    static cudaEvent_t evF = nullptr, evJ = nullptr;
    if (!s2) {
        cudaStreamCreateWithFlags(&s2, cudaStreamNonBlocking);
        cudaEventCreateWithFlags(&evF, cudaEventDisableTiming);
        cudaEventCreateWithFlags(&evJ, cudaEventDisableTiming);
        cudaFuncSetAttribute(k_qk, cudaFuncAttributeMaxDynamicSharedMemorySize,
                             QK_NSTAGE * QK_STG);
        cudaFuncSetAttribute(k_pv, cudaFuncAttributeMaxDynamicSharedMemorySize,
                             PV_NSTAGE * PV_STG);
    }

    const int P = B_ * T_ * F_;
    const float scale = 1.0f / sqrtf((float)DF);

    cudaEventRecord(evF, 0);
    cudaStreamWaitEvent(s2, evF, 0);
    k_projv<<<(P + 255) / 256, 256, 0, s2>>>(x, Wv, bv, av, gv, betav);
    cudaEventRecord(evJ, s2);

    k_projqk<<<(P + 255) / 256, 256>>>(x, Wq, bq, aq, gq, betaq,
                                       Wk, bk, ak, gk, betak);

    dim3 gqk(TNP / 128, TMPAD / 128, BH);    // 24 x 24 x 8
    k_qk<<<gqk, 128, QK_NSTAGE * QK_STG>>>(scale);

    cudaStreamWaitEvent(0, evJ, 0);

    dim3 gpv(11, TMPAD / 128, BH);           // 11 x 24 x 8  (N tiles of 96)
    k_pv<<<gpv, 128, PV_NSTAGE * PV_STG>>>();

    dim3 gfin((PTS + 127) / 128, B_);        // 1524 x 2
    k_final<<<gfin, 256>>>(x, Wp, bp, ap, gp, betap, out);
}

// round 14
// speedup vs baseline: 1.0883x; 1.0883x over previous
#include <cuda_runtime.h>
#include <cuda_fp16.h>
#include <math.h>
#include <cstdint>

#define B_    2
#define C_    64
#define T_    3000
#define F_    65
#define H_    4
#define D_    4
#define E_    16
#define DF    260
#define KQK   288      // QK K-dim padded (mult of 32)
#define EF    1040
#define NPV   1152     // V storage row width (pad cols zero)
#define KPV   3008     // PV K-dim padded (mult of 64); also P row width
#define TMPAD 3072     // M padded (mult of 128)
#define TNP   3072     // QK N tile range
#define PTS   195000   // T_*F_ points per batch
#define BH    8
#define EPS   1e-5f

// ---------------- scratch (zero-initialized .bss; pads rely on that + writes)
__device__ __align__(128) __half g_Qh [(size_t)BH * TMPAD * KQK];
__device__ __align__(128) __half g_Kh [(size_t)BH * TMPAD * KQK];
__device__ __align__(128) __half g_P  [(size_t)BH * TMPAD * KPV];  // exp(S), unnormalized
__device__ __align__(128) __half g_Vn [(size_t)BH * KPV * NPV];    // V (fp16)
__device__ __align__(128) __half g_Ohn[(size_t)BH * T_ * EF];      // normalized O, fp16
__device__ __align__(128) float  g_rsum[(size_t)BH * TMPAD];       // softmax row sums

// ---------------- helpers ----------------------------------------------------
__device__ __forceinline__ uint32_t smem_u32(const void* p) {
    uint32_t a;
    asm("{ .reg .u64 t; cvta.to.shared.u64 t, %1; cvt.u32.u64 %0, t; }" : "=r"(a) : "l"(p));
    return a;
}
__device__ __forceinline__ void cpa16(uint32_t s, const void* g) {
    asm volatile("cp.async.cg.shared.global [%0], [%1], 16;" :: "r"(s), "l"(g));
}
__device__ __forceinline__ void ldm4(uint32_t* r, uint32_t a) {
    asm volatile("ldmatrix.sync.aligned.m8n8.x4.shared.b16 {%0,%1,%2,%3}, [%4];"
                 : "=r"(r[0]), "=r"(r[1]), "=r"(r[2]), "=r"(r[3]) : "r"(a));
}
__device__ __forceinline__ void ldm4t(uint32_t* r, uint32_t a) {
    asm volatile("ldmatrix.sync.aligned.m8n8.x4.trans.shared.b16 {%0,%1,%2,%3}, [%4];"
                 : "=r"(r[0]), "=r"(r[1]), "=r"(r[2]), "=r"(r[3]) : "r"(a));
}
__device__ __forceinline__ void mma16816(float* c, const uint32_t* a, const uint32_t* b) {
    asm volatile("mma.sync.aligned.m16n8k16.row.col.f32.f16.f16.f32 "
                 "{%0,%1,%2,%3}, {%4,%5,%6,%7}, {%8,%9}, {%0,%1,%2,%3};"
                 : "+f"(c[0]), "+f"(c[1]), "+f"(c[2]), "+f"(c[3])
                 : "r"(a[0]), "r"(a[1]), "r"(a[2]), "r"(a[3]), "r"(b[0]), "r"(b[1]));
}

// dot64: 64-wide dot product against smem weights row (float4 broadcast reads,
// 4 independent chains). All lanes read the same sW address -> LDS broadcast.
__device__ __forceinline__ float dot64(const float* wrow, const float* v) {
    const float4* w4 = reinterpret_cast<const float4*>(wrow);
    float a0 = 0.f, a1 = 0.f, a2 = 0.f, a3 = 0.f;
#pragma unroll
    for (int c4 = 0; c4 < 16; c4++) {
        float4 w = w4[c4];
        a0 += w.x * v[c4 * 4 + 0];
        a1 += w.y * v[c4 * 4 + 1];
        a2 += w.z * v[c4 * 4 + 2];
        a3 += w.w * v[c4 * 4 + 3];
    }
    return (a0 + a1) + (a2 + a3);
}

// ============================================================================
// Kernel 1a: Q/K 1x1-conv + PReLU + channel-LN -> fp16. Also zeroes g_rsum.
// ============================================================================
__global__ void k_projqk(const float* __restrict__ x,
                       const float* __restrict__ Wq, const float* __restrict__ bq,
                       const float* __restrict__ aq, const float* __restrict__ gq,
                       const float* __restrict__ betaq,
                       const float* __restrict__ Wk, const float* __restrict__ bk,
                       const float* __restrict__ ak, const float* __restrict__ gk,
                       const float* __restrict__ betak) {
    __shared__ float sWq[H_ * D_ * C_];
    __shared__ float sWk[H_ * D_ * C_];
    int tid = threadIdx.x;
    for (int i = tid; i < H_ * D_ * C_; i += blockDim.x) { sWq[i] = Wq[i]; sWk[i] = Wk[i]; }
    __syncthreads();

    int p = blockIdx.x * blockDim.x + tid;
    if (p < BH * TMPAD) g_rsum[p] = 0.f;
    const int P = B_ * T_ * F_;
    if (p >= P) return;
    int b = p / (T_ * F_);
    int r = p % (T_ * F_);
    int t = r / F_;
    int f = r % F_;

    float xv[C_];
#pragma unroll
    for (int c = 0; c < C_; c++)
        xv[c] = x[((size_t)(b * C_ + c) * T_ + t) * F_ + f];

    const __half hz = __float2half(0.0f);
    for (int h = 0; h < H_; h++) {
        int bh = b * H_ + h;
        {
            float q[D_];
            float ah = aq[h];
#pragma unroll
            for (int d = 0; d < D_; d++) {
                float acc = bq[h * D_ + d] + dot64(&sWq[(h * D_ + d) * C_], xv);
                q[d] = acc >= 0.f ? acc : ah * acc;
            }
            float mu = 0.f, s2 = 0.f;
#pragma unroll
            for (int d = 0; d < D_; d++) { mu += q[d]; s2 += q[d] * q[d]; }
            mu *= (1.f / D_);
            s2 = s2 * (1.f / D_) - mu * mu;
            float inv = rsqrtf(s2 + EPS);
            size_t base = ((size_t)bh * TMPAD + t) * KQK;
#pragma unroll
            for (int d = 0; d < D_; d++)
                g_Qh[base + d * F_ + f] =
                    __float2half((q[d] - mu) * inv * gq[h * D_ + d] + betaq[h * D_ + d]);
            if (f < KQK - DF) g_Qh[base + DF + f] = hz;
        }
        {
            float q[D_];
            float ah = ak[h];
#pragma unroll
            for (int d = 0; d < D_; d++) {
                float acc = bk[h * D_ + d] + dot64(&sWk[(h * D_ + d) * C_], xv);
                q[d] = acc >= 0.f ? acc : ah * acc;
            }
            float mu = 0.f, s2 = 0.f;
#pragma unroll
            for (int d = 0; d < D_; d++) { mu += q[d]; s2 += q[d] * q[d]; }
            mu *= (1.f / D_);
            s2 = s2 * (1.f / D_) - mu * mu;
            float inv = rsqrtf(s2 + EPS);
            size_t base = ((size_t)bh * TMPAD + t) * KQK;
#pragma unroll
            for (int d = 0; d < D_; d++)
                g_Kh[base + d * F_ + f] =
                    __float2half((q[d] - mu) * inv * gk[h * D_ + d] + betak[h * D_ + d]);
            if (f < KQK - DF) g_Kh[base + DF + f] = hz;
        }
    }
}

// ============================================================================
// Kernel 1b: V 1x1-conv + PReLU + channel-LN -> fp16 (overlaps with k_qk).
// ============================================================================
__global__ void k_projv(const float* __restrict__ x,
                       const float* __restrict__ Wv, const float* __restrict__ bv,
                       const float* __restrict__ av, const float* __restrict__ gv,
                       const float* __restrict__ betav) {
    __shared__ float sWv[H_ * E_ * C_];
    int tid = threadIdx.x;
    for (int i = tid; i < H_ * E_ * C_; i += blockDim.x) sWv[i] = Wv[i];
    __syncthreads();

    int p = blockIdx.x * blockDim.x + tid;
    const int P = B_ * T_ * F_;
    if (p >= P) return;
    int b = p / (T_ * F_);
    int r = p % (T_ * F_);
    int t = r / F_;
    int f = r % F_;

    float xv[C_];
#pragma unroll
    for (int c = 0; c < C_; c++)
        xv[c] = x[((size_t)(b * C_ + c) * T_ + t) * F_ + f];

    for (int h = 0; h < H_; h++) {
        int bh = b * H_ + h;
        float v[E_];
        float ah = av[h];
#pragma unroll
        for (int e = 0; e < E_; e++) {
            float acc = bv[h * E_ + e] + dot64(&sWv[(h * E_ + e) * C_], xv);
            v[e] = acc >= 0.f ? acc : ah * acc;
        }
        float mu = 0.f, s2 = 0.f;
#pragma unroll
        for (int e = 0; e < E_; e++) { mu += v[e]; s2 += v[e] * v[e]; }
        mu *= (1.f / E_);
        s2 = s2 * (1.f / E_) - mu * mu;
        float inv = rsqrtf(s2 + EPS);
        size_t base = ((size_t)bh * KPV + t) * NPV;
#pragma unroll
        for (int e = 0; e < E_; e++)
            g_Vn[base + e * F_ + f] =
                __float2half((v[e] - mu) * inv * gv[h * E_ + e] + betav[h * E_ + e]);
    }
}

// ============================================================================
// Kernel 2a: QK GEMM (R8/R10 proven config: 256 thr, 8 warps 4m x 2n,
// warp tile 32x64, BK=32, 4-stage). P = fp16(exp(scale*acc)) + rsum atomics.
// ============================================================================
#define QK_ASTG 10240
#define QK_BROW 80
#define QK_STG  (QK_ASTG + 128 * QK_BROW)   // 20480
#define QK_NSTAGE 4

__global__ void __launch_bounds__(256, 2) k_qk(float scale) {
    extern __shared__ __align__(128) char smem[];
    const int tid = threadIdx.x;
    const int wid = tid >> 5, lane = tid & 31;
    const int wm = wid & 3, wn = wid >> 2;     // 4m x 2n
    const int bh = blockIdx.z, m0 = blockIdx.y * 128, n0 = blockIdx.x * 128;

    const __half* Ag = g_Qh + (size_t)bh * TMPAD * KQK;
    const __half* Bg = g_Kh + (size_t)bh * TMPAD * KQK;
    const int chunks = KQK / 32;   // 9

    const uint32_t sbase = smem_u32(smem);

    float acc[2][8][4];
#pragma unroll
    for (int i = 0; i < 2; i++)
#pragma unroll
        for (int j = 0; j < 8; j++)
#pragma unroll
            for (int q = 0; q < 4; q++) acc[i][j][q] = 0.f;

    auto load_stage = [&](int st, int c) {
        uint32_t sa = sbase + st * QK_STG;
        uint32_t sb = sa + QK_ASTG;
        int k0 = c * 32;
#pragma unroll
        for (int j = 0; j < 2; j++) {
            int idx = tid * 2 + j;
            int row = idx >> 2, g = idx & 3;
            cpa16(sa + row * 80 + g * 16, Ag + (size_t)(m0 + row) * KQK + k0 + g * 8);
            cpa16(sb + row * 80 + g * 16, Bg + (size_t)(n0 + row) * KQK + k0 + g * 8);
        }
    };

    auto compute_stage = [&](int st) {
        uint32_t sa = sbase + st * QK_STG;
        uint32_t sb = sa + QK_ASTG;
#pragma unroll
        for (int kk = 0; kk < 32; kk += 16) {
            uint32_t a[2][4];
#pragma unroll
            for (int mt = 0; mt < 2; mt++) {
                int row = wm * 32 + mt * 16 + (lane & 15);
                ldm4(a[mt], sa + row * 80 + (kk + ((lane >> 4) << 3)) * 2);
            }
            uint32_t bfr[4][4];
#pragma unroll
            for (int bt = 0; bt < 4; bt++) {
                int row = wn * 64 + bt * 16 + ((lane >> 4) << 3) + (lane & 7);
                ldm4(bfr[bt], sb + row * 80 + (kk + ((lane >> 3) & 1) * 8) * 2);
            }
#pragma unroll
            for (int mt = 0; mt < 2; mt++)
#pragma unroll
                for (int nt = 0; nt < 8; nt++)
                    mma16816(acc[mt][nt], a[mt], &bfr[nt >> 1][(nt & 1) * 2]);
        }
    };

    load_stage(0, 0);
    asm volatile("cp.async.commit_group;" ::: "memory");
    load_stage(1, 1);
    asm volatile("cp.async.commit_group;" ::: "memory");
    load_stage(2, 2);
    asm volatile("cp.async.commit_group;" ::: "memory");

    int st = 0;
    for (int c = 0; c < chunks; c++) {
        if (c >= chunks - 1)      asm volatile("cp.async.wait_group 0;" ::: "memory");
        else if (c == chunks - 2) asm volatile("cp.async.wait_group 1;" ::: "memory");
        else                      asm volatile("cp.async.wait_group 2;" ::: "memory");
        __syncthreads();
        if (c + 3 < chunks) {
            int st2 = st + 3; if (st2 >= QK_NSTAGE) st2 -= QK_NSTAGE;
            load_stage(st2, c + 3);
            asm volatile("cp.async.commit_group;" ::: "memory");
        } else {
            asm volatile("cp.async.commit_group;" ::: "memory");
        }
        compute_stage(st);
        if (++st == QK_NSTAGE) st = 0;
    }

    // epilogue: exp, store P, rsum atomics
#pragma unroll
    for (int mt = 0; mt < 2; mt++) {
        int r0 = m0 + wm * 32 + mt * 16 + (lane >> 2);
        float rs0 = 0.f, rs1 = 0.f;
#pragma unroll
        for (int nt = 0; nt < 8; nt++) {
            int cc = n0 + wn * 64 + nt * 8 + (lane & 3) * 2;
            float* a4 = acc[mt][nt];
            float e0 = (cc     < T_) ? __expf(a4[0] * scale) : 0.f;
            float e1 = (cc + 1 < T_) ? __expf(a4[1] * scale) : 0.f;
            float e2 = (cc     < T_) ? __expf(a4[2] * scale) : 0.f;
            float e3 = (cc + 1 < T_) ? __expf(a4[3] * scale) : 0.f;
            rs0 += e0 + e1;
            rs1 += e2 + e3;
            if (cc < KPV) {
                __half2 h0, h1;
                h0.x = __float2half(e0); h0.y = __float2half(e1);
                h1.x = __float2half(e2); h1.y = __float2half(e3);
                *reinterpret_cast<__half2*>(&g_P[((size_t)bh * TMPAD + r0) * KPV + cc]) = h0;
                *reinterpret_cast<__half2*>(&g_P[((size_t)bh * TMPAD + r0 + 8) * KPV + cc]) = h1;
            }
        }
        rs0 += __shfl_xor_sync(~0u, rs0, 1); rs0 += __shfl_xor_sync(~0u, rs0, 2);
        rs1 += __shfl_xor_sync(~0u, rs1, 1); rs1 += __shfl_xor_sync(~0u, rs1, 2);
        if ((lane & 3) == 0) {
            atomicAdd(&g_rsum[bh * TMPAD + r0], rs0);
            atomicAdd(&g_rsum[bh * TMPAD + r0 + 8], rs1);
        }
    }
}

// ============================================================================
// Kernel 2b: PV GEMM (R11 proven config: 128 thr, 4 warps 2m x 2n,
// warp tile 64x48, BK=64, 3-stage, regs free). O=(P@Vn)*(1/rsum) -> fp16.
// ============================================================================
#define PV_AROW 144
#define PV_ASTG (128 * PV_AROW)      // 18432
#define PV_BROW 208
#define PV_BSTG (64 * PV_BROW)       // 13312
#define PV_STG  (PV_ASTG + PV_BSTG)  // 31744
#define PV_NSTAGE 3

__global__ void __launch_bounds__(128, 2) k_pv() {
    extern __shared__ __align__(128) char smem[];
    const int tid = threadIdx.x;
    const int wid = tid >> 5, lane = tid & 31;
    const int wm = wid & 1, wn = wid >> 1;     // 2m x 2n
    const int bh = blockIdx.z, m0 = blockIdx.y * 128, n0 = blockIdx.x * 96;

    const __half* Ag = g_P + (size_t)bh * TMPAD * KPV;
    const __half* Bg = g_Vn + (size_t)bh * KPV * NPV;
    const int chunks = KPV / 64;    // 47

    const uint32_t sbase = smem_u32(smem);

    float acc[4][6][4];
#pragma unroll
    for (int i = 0; i < 4; i++)
#pragma unroll
        for (int j = 0; j < 6; j++)
#pragma unroll
            for (int q = 0; q < 4; q++) acc[i][j][q] = 0.f;

    auto load_stage = [&](int st, int c) {
        uint32_t sa = sbase + st * PV_STG;
        uint32_t sb = sa + PV_ASTG;
        int k0 = c * 64;
#pragma unroll
        for (int j = 0; j < 8; j++) {
            int idx = tid + j * 128;
            int row = idx >> 3, g = idx & 7;
            cpa16(sa + row * PV_AROW + g * 16, Ag + (size_t)(m0 + row) * KPV + k0 + g * 8);
        }
#pragma unroll
        for (int j = 0; j < 7; j++) {
            int idx = tid + j * 128;
            if (idx < 64 * 13) {
                int row = idx / 13, g = idx % 13;
                cpa16(sb + row * PV_BROW + g * 16, Bg + (size_t)(k0 + row) * NPV + n0 + g * 8);
            }
        }
    };

    auto compute_stage = [&](int st) {
        uint32_t sa = sbase + st * PV_STG;
        uint32_t sb = sa + PV_ASTG;
#pragma unroll
        for (int kk = 0; kk < 64; kk += 16) {
            uint32_t a[4][4];
#pragma unroll
            for (int mt = 0; mt < 4; mt++) {
                int row = wm * 64 + mt * 16 + (lane & 15);
                ldm4(a[mt], sa + row * PV_AROW + (kk + ((lane >> 4) << 3)) * 2);
            }
            uint32_t bfr[3][4];
#pragma unroll
            for (int bt = 0; bt < 3; bt++) {
                int krow = kk + (lane & 15);
                int ncol = wn * 48 + bt * 16 + ((lane >> 4) << 3);
                ldm4t(bfr[bt], sb + krow * PV_BROW + ncol * 2);
            }
#pragma unroll
            for (int mt = 0; mt < 4; mt++)
#pragma unroll
                for (int nt = 0; nt < 6; nt++)
                    mma16816(acc[mt][nt], a[mt], &bfr[nt >> 1][(nt & 1) * 2]);
        }
    };

    load_stage(0, 0);
    asm volatile("cp.async.commit_group;" ::: "memory");
    load_stage(1, 1);
    asm volatile("cp.async.commit_group;" ::: "memory");

    int st = 0;
    for (int c = 0; c < chunks; c++) {
        if (c == chunks - 1) asm volatile("cp.async.wait_group 0;" ::: "memory");
        else                 asm volatile("cp.async.wait_group 1;" ::: "memory");
        __syncthreads();
        if (c + 2 < chunks) {
            int st2 = st + 2; if (st2 >= PV_NSTAGE) st2 -= PV_NSTAGE;
            load_stage(st2, c + 2);
            asm volatile("cp.async.commit_group;" ::: "memory");
        } else {
            asm volatile("cp.async.commit_group;" ::: "memory");
        }
        compute_stage(st);
        if (++st == PV_NSTAGE) st = 0;
    }

    // epilogue: normalize by row sums, write fp16
#pragma unroll
    for (int mt = 0; mt < 4; mt++) {
        int r0 = m0 + wm * 64 + mt * 16 + (lane >> 2);
        float ri0 = 1.0f / g_rsum[bh * TMPAD + r0];
        float ri1 = 1.0f / g_rsum[bh * TMPAD + r0 + 8];
#pragma unroll
        for (int nt = 0; nt < 6; nt++) {
            int cc = n0 + wn * 48 + nt * 8 + (lane & 3) * 2;
            float* a4 = acc[mt][nt];
            if (cc < EF) {
                if (r0 < T_) {
                    __half2 h;
                    h.x = __float2half(a4[0] * ri0);
                    h.y = __float2half(a4[1] * ri0);
                    *reinterpret_cast<__half2*>(&g_Ohn[((size_t)bh * T_ + r0) * EF + cc]) = h;
                }
                if (r0 + 8 < T_) {
                    __half2 h;
                    h.x = __float2half(a4[2] * ri1);
                    h.y = __float2half(a4[3] * ri1);
                    *reinterpret_cast<__half2*>(&g_Ohn[((size_t)bh * T_ + r0 + 8) * EF + cc]) = h;
                }
            }
        }
    }
}

// ============================================================================
// Kernel 3: tensorized final conv: out = LN(PReLU(Wp @ Ohn + bp)) + x.
// ============================================================================
#define RSX 136
#define RSW 72
__global__ void __launch_bounds__(256) k_final(const float* __restrict__ x,
                        const float* __restrict__ Wp, const float* __restrict__ bp,
                        const float* __restrict__ ap, const float* __restrict__ gp,
                        const float* __restrict__ betap,
                        float* __restrict__ out) {
    __shared__ __align__(128) __half sX[64 * RSX];
    __shared__ __align__(128) __half sW[64 * RSW];
    __shared__ float sRed[2][4][128];

    const int tid = threadIdx.x;
    const int wid = tid >> 5, lane = tid & 31;
    const int wm = wid & 3, wn = wid >> 2;
    const int b = blockIdx.y, n0 = blockIdx.x * 128;

    for (int i = tid; i < C_ * C_; i += 256)
        sW[(i >> 6) * RSW + (i & 63)] = __float2half(Wp[i]);
    for (int i = tid; i < C_ * 128; i += 256) {
        int c = i >> 7, n = i & 127;
        int pp = n0 + n;
        __half v = __float2half(0.f);
        if (pp < PTS) {
            int t = pp / F_, f = pp - t * F_;
            v = g_Ohn[((size_t)(b * H_ + (c >> 4)) * T_ + t) * EF + (c & 15) * F_ + f];
        }
        sX[c * RSX + n] = v;
    }
    __syncthreads();

    const uint32_t uW = smem_u32(sW), uX = smem_u32(sX);

    uint32_t aAll[4][4];
#pragma unroll
    for (int kk = 0; kk < 4; kk++)
        ldm4(aAll[kk], uW + (wm * 16 + (lane & 15)) * (RSW * 2)
                          + (kk * 16 + ((lane >> 4) << 3)) * 2);

    float acc[8][4];
#pragma unroll
    for (int j = 0; j < 8; j++)
#pragma unroll
        for (int q = 0; q < 4; q++) acc[j][q] = 0.f;

#pragma unroll
    for (int kk = 0; kk < 4; kk++) {
        uint32_t bfr[4][4];
#pragma unroll
        for (int bt = 0; bt < 4; bt++)
            ldm4t(bfr[bt], uX + (kk * 16 + (lane & 15)) * (RSX * 2)
                              + (wn * 64 + bt * 16 + ((lane >> 4) << 3)) * 2);
#pragma unroll
        for (int nt = 0; nt < 8; nt++)
            mma16816(acc[nt], aAll[kk], &bfr[nt >> 1][(nt & 1) * 2]);
    }

    const int o = wm * 16 + (lane >> 2);
    const float b0 = bp[o], b1 = bp[o + 8];
    const float a = ap[0];
#pragma unroll
    for (int nt = 0; nt < 8; nt++) {
        float* a4 = acc[nt];
        float y0 = a4[0] + b0; y0 = y0 >= 0.f ? y0 : a * y0;
        float y1 = a4[1] + b0; y1 = y1 >= 0.f ? y1 : a * y1;
        float y2 = a4[2] + b1; y2 = y2 >= 0.f ? y2 : a * y2;
        float y3 = a4[3] + b1; y3 = y3 >= 0.f ? y3 : a * y3;
        a4[0] = y0; a4[1] = y1; a4[2] = y2; a4[3] = y3;
        float s0 = y0 + y2, s1 = y1 + y3;
        float q0 = y0 * y0 + y2 * y2, q1 = y1 * y1 + y3 * y3;
#pragma unroll
        for (int m = 4; m <= 16; m <<= 1) {
            s0 += __shfl_xor_sync(~0u, s0, m);
            s1 += __shfl_xor_sync(~0u, s1, m);
            q0 += __shfl_xor_sync(~0u, q0, m);
            q1 += __shfl_xor_sync(~0u, q1, m);
        }
        if ((lane >> 2) == 0) {
            int cl = wn * 64 + nt * 8 + (lane & 3) * 2;
            sRed[0][wm][cl] = s0; sRed[0][wm][cl + 1] = s1;
            sRed[1][wm][cl] = q0; sRed[1][wm][cl + 1] = q1;
        }
    }
    __syncthreads();

    const float g0 = gp[o], g1 = gp[o + 8];
    const float be0 = betap[o], be1 = betap[o + 8];
#pragma unroll
    for (int nt = 0; nt < 8; nt++) {
        int cl = wn * 64 + nt * 8 + (lane & 3) * 2;
        int pp = n0 + cl;
        if (pp >= PTS) continue;
        float mu0 = 0.f, mu1 = 0.f, sq0 = 0.f, sq1 = 0.f;
#pragma unroll
        for (int w = 0; w < 4; w++) {
            mu0 += sRed[0][w][cl];     mu1 += sRed[0][w][cl + 1];
            sq0 += sRed[1][w][cl];     sq1 += sRed[1][w][cl + 1];
        }
        mu0 *= (1.f / C_); mu1 *= (1.f / C_);
        float v0 = sq0 * (1.f / C_) - mu0 * mu0;
        float v1 = sq1 * (1.f / C_) - mu1 * mu1;
        float i0 = rsqrtf(v0 + EPS), i1 = rsqrtf(v1 + EPS);
        float* a4 = acc[nt];
        size_t idx0 = ((size_t)(b * C_ + o)) * PTS + pp;
        size_t idx1 = ((size_t)(b * C_ + o + 8)) * PTS + pp;
        float2 xr0 = *reinterpret_cast<const float2*>(&x[idx0]);
        float2 xr1 = *reinterpret_cast<const float2*>(&x[idx1]);
        float2 o0, o1;
        o0.x = (a4[0] - mu0) * i0 * g0 + be0 + xr0.x;
        o0.y = (a4[1] - mu1) * i1 * g0 + be0 + xr0.y;
        o1.x = (a4[2] - mu0) * i0 * g1 + be1 + xr1.x;
        o1.y = (a4[3] - mu1) * i1 * g1 + be1 + xr1.y;
        *reinterpret_cast<float2*>(&out[idx0]) = o0;
        *reinterpret_cast<float2*>(&out[idx1]) = o1;
    }
}

// ============================================================================
extern "C" void kernel_launch(void* const* d_in, const int* in_sizes, int n_in,
                              void* d_out, int out_size) {
    const float* x     = (const float*)d_in[0];
    const float* Wq    = (const float*)d_in[1];
    const float* bq    = (const float*)d_in[2];
    const float* aq    = (const float*)d_in[3];
    const float* gq    = (const float*)d_in[4];
    const float* betaq = (const float*)d_in[5];
    const float* Wk    = (const float*)d_in[6];
    const float* bk    = (const float*)d_in[7];
    const float* ak    = (const float*)d_in[8];
    const float* gk    = (const float*)d_in[9];
    const float* betak = (const float*)d_in[10];
    const float* Wv    = (const float*)d_in[11];
    const float* bv    = (const float*)d_in[12];
    const float* av    = (const float*)d_in[13];
    const float* gv    = (const float*)d_in[14];
    const float* betav = (const float*)d_in[15];
    const float* Wp    = (const float*)d_in[16];
    const float* bp    = (const float*)d_in[17];
    const float* ap    = (const float*)d_in[18];
    const float* gp    = (const float*)d_in[19];
    const float* betap = (const float*)d_in[20];
    float* out = (float*)d_out;

    static cudaStream_t s2 = nullptr;
    static cudaEvent_t evF = nullptr, evJ = nullptr;
    if (!s2) {
        cudaStreamCreateWithFlags(&s2, cudaStreamNonBlocking);
        cudaEventCreateWithFlags(&evF, cudaEventDisableTiming);
        cudaEventCreateWithFlags(&evJ, cudaEventDisableTiming);
        cudaFuncSetAttribute(k_qk, cudaFuncAttributeMaxDynamicSharedMemorySize,
                             QK_NSTAGE * QK_STG);
        cudaFuncSetAttribute(k_pv, cudaFuncAttributeMaxDynamicSharedMemorySize,
                             PV_NSTAGE * PV_STG);
    }

    const int P = B_ * T_ * F_;
    const float scale = 1.0f / sqrtf((float)DF);

    cudaEventRecord(evF, 0);
    cudaStreamWaitEvent(s2, evF, 0);
    k_projv<<<(P + 255) / 256, 256, 0, s2>>>(x, Wv, bv, av, gv, betav);
    cudaEventRecord(evJ, s2);

    k_projqk<<<(P + 255) / 256, 256>>>(x, Wq, bq, aq, gq, betaq,
                                       Wk, bk, ak, gk, betak);

    dim3 gqk(TNP / 128, TMPAD / 128, BH);    // 24 x 24 x 8
    k_qk<<<gqk, 256, QK_NSTAGE * QK_STG>>>(scale);

    cudaStreamWaitEvent(0, evJ, 0);

    dim3 gpv(11, TMPAD / 128, BH);           // 11 x 24 x 8  (N tiles of 96)
    k_pv<<<gpv, 128, PV_NSTAGE * PV_STG>>>();

    dim3 gfin((PTS + 127) / 128, B_);        // 1524 x 2
    k_final<<<gfin, 256>>>(x, Wp, bp, ap, gp, betap, out);
}